// round 1
// baseline (speedup 1.0000x reference)
#include <cuda_runtime.h>

// YOLOLoss: input (32,75,104,104) f32, targets (32,50,5) f32 -> 6 loss scalars.
// Key insight: only the conf channel (4.15 MB) needs a dense pass; everything
// else is nonzero only at <=1600 positive cells.

#define BSZ   32
#define NA    3
#define NT    50
#define HH    104
#define WW    104
#define HWSZ  (HH*WW)            // 10816
#define NCH   75
#define NCLS  20                 // NUM_CLASSES-1
#define NCELL ((double)(BSZ*NA*HWSZ))

__device__ double g_acc[8];      // sx, sy, sw, sh, sconf_pos, snoobj, scls, npos

__device__ __forceinline__ float clogf_(float p) {
    // matches jnp.clip(jnp.log(p), -100, None); __logf(0) = -inf -> -100
    return fmaxf(__logf(p), -100.0f);
}
__device__ __forceinline__ float sigm(float z) {
    return 1.0f / (1.0f + __expf(-z));
}

__global__ void yolo_zero_acc() {
    if (threadIdx.x < 8) g_acc[threadIdx.x] = 0.0;
}

__global__ __launch_bounds__(256) void yolo_main(const float* __restrict__ in,
                                                 const float* __restrict__ tg) {
    __shared__ int   s_meta[NT];                 // packed: pos(14)|best_n(2)|nz(3)|cls(5)
    __shared__ float s_tx[NT], s_ty[NT], s_tw[NT], s_th[NT];

    const int b   = blockIdx.y;
    const int tid = threadIdx.x;

    // ---- per-target preprocessing (threads 0..49) ----
    if (tid < NT) {
        const float* t = tg + ((size_t)b * NT + tid) * 5;
        float t0 = t[0], t1 = t[1], t2 = t[2], t3 = t[3], t4 = t[4];
        float ssum = t0 + t1 + t2 + t3 + t4;
        int   meta = 0x7FFFFFFF;                 // invalid: low 14 bits = 16383 > any pos
        float txv = 0.f, tyv = 0.f, twv = 0.f, thv = 0.f;
        if (ssum > 0.0f) {
            float gx = t0 * (float)WW, gy = t1 * (float)HH;
            float gw = t2 * (float)WW, gh = t3 * (float)HH;
            int gi = (int)gx, gj = (int)gy;
            const float aw[3] = {14.5f, 19.5f, 46.625f};   // ANCHORS / stride(=8)
            const float ah[3] = {11.25f, 24.75f, 40.75f};
            float area_gt = (gw + 1.0f) * (gh + 1.0f);
            float best = -1.0f; int bn = 0; int nz = 0;
            #pragma unroll
            for (int a = 0; a < 3; a++) {
                float inter = fmaxf(fminf(gw, aw[a]) + 1.0f, 0.0f) *
                              fmaxf(fminf(gh, ah[a]) + 1.0f, 0.0f);
                float iou = inter / (area_gt + (aw[a] + 1.0f) * (ah[a] + 1.0f) - inter + 1e-16f);
                if (iou > best) { best = iou; bn = a; }      // argmax: first max wins
                if (iou > 0.5f) nz |= (1 << a);              // IGNORE_THRESH
            }
            txv = gx - (float)gi;
            tyv = gy - (float)gj;
            twv = __logf(gw / aw[bn] + 1e-16f);
            thv = __logf(gh / ah[bn] + 1e-16f);
            int cls = (int)t4;
            meta = (gj * WW + gi) | (bn << 14) | (nz << 16) | (cls << 19);
        }
        s_meta[tid] = meta;
        s_tx[tid] = txv; s_ty[tid] = tyv; s_tw[tid] = twv; s_th[tid] = thv;
    }
    __syncthreads();

    double sx = 0, sy = 0, sw = 0, sh = 0, sconf = 0, snoobj = 0, scls = 0, snpos = 0;

    const int pos = blockIdx.x * 256 + tid;      // pos = i*WW + j
    if (pos < HWSZ) {
        // scan targets: winner per anchor (last t wins -> matches serial scatter),
        // ignore bits (union), class union per anchor (tcls 5-D scatter -> union)
        int win0 = -1, win1 = -1, win2 = -1;
        unsigned cm0 = 0, cm1 = 0, cm2 = 0;
        int nz = 0;
        #pragma unroll 1
        for (int t = 0; t < NT; t++) {
            int m = s_meta[t];                   // broadcast LDS
            if ((m & 0x3FFF) == pos) {
                nz |= (m >> 16) & 7;
                int a = (m >> 14) & 3;
                unsigned cbit = 1u << ((m >> 19) & 31);
                if      (a == 0) { win0 = t; cm0 |= cbit; }
                else if (a == 1) { win1 = t; cm1 |= cbit; }
                else             { win2 = t; cm2 |= cbit; }
            }
        }

        const float* inb = in + (size_t)b * NCH * HWSZ + pos;
        #pragma unroll
        for (int a = 0; a < 3; a++) {
            const float* ch = inb + (size_t)a * 25 * HWSZ;
            float conf = sigm(ch[4 * HWSZ]);
            // noobj term: cells NOT zeroed by the ignore scatter
            if (!((nz >> a) & 1))
                snoobj += (double)(-clogf_(1.0f - conf));

            int w = (a == 0) ? win0 : ((a == 1) ? win1 : win2);
            if (w >= 0) {
                unsigned cm = (a == 0) ? cm0 : ((a == 1) ? cm1 : cm2);
                snpos += 1.0;
                sconf += (double)(-clogf_(conf));            // tconf = 1 at positives
                float px  = sigm(ch[0]);
                float py  = sigm(ch[HWSZ]);
                float txv = s_tx[w], tyv = s_ty[w];
                sx += (double)(-(txv * clogf_(px) + (1.0f - txv) * clogf_(1.0f - px)));
                sy += (double)(-(tyv * clogf_(py) + (1.0f - tyv) * clogf_(1.0f - py)));
                float dw = ch[2 * HWSZ] - s_tw[w];
                float dh = ch[3 * HWSZ] - s_th[w];
                sw += (double)(dw * dw);
                sh += (double)(dh * dh);
                #pragma unroll 1
                for (int c = 0; c < NCLS; c++) {
                    float p  = sigm(ch[(5 + c) * HWSZ]);
                    float tt = ((cm >> c) & 1) ? 1.0f : 0.0f;
                    scls += (double)(-(tt * clogf_(p) + (1.0f - tt) * clogf_(1.0f - p)));
                }
            }
        }
    }

    // ---- block reduction: warp shuffle, then 8 lanes sum 8 warp partials ----
    __shared__ double s_warp[8][8];              // [warp][accumulator]
    double vals[8] = {sx, sy, sw, sh, sconf, snoobj, scls, snpos};
    const int lane = tid & 31, wrp = tid >> 5;
    #pragma unroll
    for (int k = 0; k < 8; k++) {
        double v = vals[k];
        #pragma unroll
        for (int off = 16; off > 0; off >>= 1)
            v += __shfl_down_sync(0xFFFFFFFFu, v, off);
        if (lane == 0) s_warp[wrp][k] = v;
    }
    __syncthreads();
    if (tid < 8) {
        double v = 0.0;
        #pragma unroll
        for (int wv = 0; wv < 8; wv++) v += s_warp[wv][tid];
        atomicAdd(&g_acc[tid], v);               // no return use -> REDG
    }
}

__global__ void yolo_finalize(float* __restrict__ out) {
    double sx = g_acc[0], sy = g_acc[1], sw = g_acc[2], sh = g_acc[3];
    double sconf = g_acc[4], snoobj = g_acc[5], scls = g_acc[6], npos = g_acc[7];
    out[0] = (float)(2.5 * sx / NCELL);                      // loss_x
    out[1] = (float)(2.5 * sy / NCELL);                      // loss_y
    out[2] = (float)(2.5 * sw / NCELL);                      // loss_w
    out[3] = (float)(2.5 * sh / NCELL);                      // loss_h
    out[4] = (float)((sconf + 0.5 * snoobj) / NCELL);        // loss_obj
    out[5] = (float)(scls / fmax(npos * 20.0, 1.0));         // loss_cls
}

extern "C" void kernel_launch(void* const* d_in, const int* in_sizes, int n_in,
                              void* d_out, int out_size) {
    const float* in = (const float*)d_in[0];   // (32,75,104,104)
    const float* tg = (const float*)d_in[1];   // (32,50,5)
    float* out = (float*)d_out;                // 6 floats

    yolo_zero_acc<<<1, 8>>>();
    dim3 grid((HWSZ + 255) / 256, BSZ);        // (43, 32)
    yolo_main<<<grid, 256>>>(in, tg);
    yolo_finalize<<<1, 1>>>(out);
}

// round 2
// speedup vs baseline: 3.0935x; 3.0935x over previous
#include <cuda_runtime.h>

// YOLOLoss fused single-kernel version.
// input (32,75,104,104) f32, targets (32,50,5) f32 -> 6 loss scalars.
// Dense work = conf channels only (4.15 MB); everything else lives at <=1600
// positive cells handled as per-block compacted tasks.

#define BSZ     32
#define NT      50
#define HH      104
#define WW      104
#define HW      (HH*WW)                 // 10816
#define NCLS    20
#define BLK_POS 1024                    // positions per block (256 thr x 4)
#define NBX     ((HW + BLK_POS - 1) / BLK_POS)   // 11
#define NBLK    (NBX * BSZ)             // 352
#define NCELL   ((double)(BSZ * 3 * HW))

__device__ double   g_part[NBLK][8];
__device__ unsigned g_ctr;              // zero at load; reset by last block

__device__ __forceinline__ float clogf_(float p) {
    return fmaxf(__logf(p), -100.0f);   // clip(log(p), -100)
}
__device__ __forceinline__ float sigm(float z) {
    return 1.0f / (1.0f + __expf(-z));
}

__global__ __launch_bounds__(256) void yolo_fused(const float* __restrict__ in,
                                                  const float* __restrict__ tg,
                                                  float* __restrict__ out)
{
    __shared__ int    s_meta[NT];       // pos(14)|bn(2)|nz(3)|cls(5)
    __shared__ float  s_tx[NT], s_ty[NT], s_tw[NT], s_th[NT];
    __shared__ int    s_task[NT];       // t(6) | cm<<6   (deduped positives in block)
    __shared__ int    s_ign[NT];        // pos(14) | nz(3)<<14
    __shared__ int    s_ntask, s_nign, s_last;
    __shared__ float  s_wsum[8][8];
    __shared__ double s_tot[8];

    const int b   = blockIdx.y;
    const int tid = threadIdx.x;
    const int P0  = blockIdx.x * BLK_POS;
    const int lane = tid & 31, wrp = tid >> 5;

    if (tid == 0) { s_ntask = 0; s_nign = 0; }

    // ---- per-target preprocessing (threads 0..49) ----
    if (tid < NT) {
        const float* t = tg + ((size_t)b * NT + tid) * 5;
        float t0 = t[0], t1 = t[1], t2 = t[2], t3 = t[3], t4 = t[4];
        int   meta = 0x7FFFFFFF;        // invalid: low14 = 16383 > any pos
        float txv = 0.f, tyv = 0.f, twv = 0.f, thv = 0.f;
        if (t0 + t1 + t2 + t3 + t4 > 0.0f) {
            float gx = t0 * (float)WW, gy = t1 * (float)HH;
            float gw = t2 * (float)WW, gh = t3 * (float)HH;
            int gi = (int)gx, gj = (int)gy;
            const float aw[3] = {14.5f, 19.5f, 46.625f};   // ANCHORS / 8
            const float ah[3] = {11.25f, 24.75f, 40.75f};
            float area = (gw + 1.0f) * (gh + 1.0f);
            float best = -1.0f; int bn = 0, nz = 0;
            #pragma unroll
            for (int a = 0; a < 3; a++) {
                float inter = fmaxf(fminf(gw, aw[a]) + 1.0f, 0.0f) *
                              fmaxf(fminf(gh, ah[a]) + 1.0f, 0.0f);
                float iou = inter / (area + (aw[a] + 1.0f) * (ah[a] + 1.0f) - inter + 1e-16f);
                if (iou > best) { best = iou; bn = a; }
                if (iou > 0.5f) nz |= (1 << a);
            }
            txv = gx - (float)gi;
            tyv = gy - (float)gj;
            twv = __logf(gw / aw[bn] + 1e-16f);
            thv = __logf(gh / ah[bn] + 1e-16f);
            meta = (gj * WW + gi) | (bn << 14) | (nz << 16) | (((int)t4) << 19);
        }
        s_meta[tid] = meta;
        s_tx[tid] = txv; s_ty[tid] = tyv; s_tw[tid] = twv; s_th[tid] = thv;
    }
    __syncthreads();

    // ---- block-filter + dedup (threads 0..49) ----
    if (tid < NT) {
        int m = s_meta[tid];
        int pos = m & 0x3FFF;
        if (pos >= P0 && pos < P0 + BLK_POS) {          // pos<HW implied for valid
            int nz = (m >> 16) & 7;
            if (nz) s_ign[atomicAdd(&s_nign, 1)] = pos | (nz << 14);

            // survivor = LAST duplicate at same (pos, anchor); union class bits
            int mya = (m >> 14) & 3;
            unsigned cm = 1u << ((m >> 19) & 31);
            bool alive = true;
            for (int u = 0; u < NT; u++) {
                if (u == tid) continue;
                int mu = s_meta[u];
                if ((mu & 0x3FFF) == pos && ((mu >> 14) & 3) == mya) {
                    if (u > tid) alive = false;
                    else         cm |= 1u << ((mu >> 19) & 31);
                }
            }
            if (alive) s_task[atomicAdd(&s_ntask, 1)] = tid | (int)(cm << 6);
        }
    }
    __syncthreads();

    float a_x = 0.f, a_y = 0.f, a_w = 0.f, a_h = 0.f;
    float a_cf = 0.f, a_no = 0.f, a_cl = 0.f, a_np = 0.f;

    // ---- dense noobj pass: 4 positions per thread, conf channel only ----
    const int p0 = P0 + tid * 4;
    if (p0 < HW) {                       // HW%4==0 -> full quads only
        int nzp = 0;                     // bit q*3+a
        const int ni = s_nign;
        for (int k = 0; k < ni; k++) {
            int e = s_ign[k];
            int d = (e & 0x3FFF) - p0;
            if ((unsigned)d < 4u) nzp |= ((e >> 14) & 7) << (d * 3);
        }
        const float* base = in + (size_t)b * 75 * HW;
        #pragma unroll
        for (int a = 0; a < 3; a++) {
            float4 c4 = *(const float4*)(base + (size_t)(a * 25 + 4) * HW + p0);
            float cv[4] = {c4.x, c4.y, c4.z, c4.w};
            #pragma unroll
            for (int q = 0; q < 4; q++)
                if (!((nzp >> (q * 3 + a)) & 1))
                    a_no += -clogf_(1.0f - sigm(cv[q]));
        }
    }

    // ---- positive-cell tasks: one thread per deduped positive ----
    if (tid < s_ntask) {
        int e = s_task[tid];
        int t = e & 63;
        unsigned cm = ((unsigned)e) >> 6;
        int m = s_meta[t];
        int pos = m & 0x3FFF, a = (m >> 14) & 3;
        const float* ch = in + (size_t)b * 75 * HW + (size_t)(a * 25) * HW + pos;
        // batch all 25 loads (MLP) before compute
        float vx = ch[0], vy = ch[HW], vw = ch[2 * HW], vh = ch[3 * HW], vc = ch[4 * HW];
        float pcls[NCLS];
        #pragma unroll
        for (int c = 0; c < NCLS; c++) pcls[c] = ch[(size_t)(5 + c) * HW];

        float px = sigm(vx), py = sigm(vy), cf = sigm(vc);
        float txv = s_tx[t], tyv = s_ty[t];
        a_x = -(txv * clogf_(px) + (1.0f - txv) * clogf_(1.0f - px));
        a_y = -(tyv * clogf_(py) + (1.0f - tyv) * clogf_(1.0f - py));
        float dw = vw - s_tw[t], dh = vh - s_th[t];
        a_w = dw * dw;
        a_h = dh * dh;
        a_cf = -clogf_(cf);
        a_np = 1.0f;
        float scl = 0.f;
        #pragma unroll
        for (int c = 0; c < NCLS; c++) {
            float p  = sigm(pcls[c]);
            float pu = ((cm >> c) & 1) ? p : (1.0f - p);   // select before log
            scl += -clogf_(pu);
        }
        a_cl = scl;
    }

    // ---- block reduction (float tree), block partial -> double ----
    float vals[8] = {a_x, a_y, a_w, a_h, a_cf, a_no, a_cl, a_np};
    #pragma unroll
    for (int k = 0; k < 8; k++) {
        float v = vals[k];
        #pragma unroll
        for (int off = 16; off > 0; off >>= 1)
            v += __shfl_down_sync(0xFFFFFFFFu, v, off);
        if (lane == 0) s_wsum[wrp][k] = v;
    }
    __syncthreads();
    const int gb = b * NBX + blockIdx.x;
    if (tid < 8) {
        float v = 0.f;
        #pragma unroll
        for (int w8 = 0; w8 < 8; w8++) v += s_wsum[w8][tid];
        g_part[gb][tid] = (double)v;
    }
    __threadfence();
    __syncthreads();
    if (tid == 0) s_last = (atomicAdd(&g_ctr, 1) == NBLK - 1);
    __syncthreads();

    // ---- last block finalizes ----
    if (s_last) {
        __threadfence();                 // order with producers' fences
        double v = 0.0;                  // warp wrp owns accumulator wrp
        for (int i = lane; i < NBLK; i += 32) v += g_part[i][wrp];
        #pragma unroll
        for (int off = 16; off > 0; off >>= 1)
            v += __shfl_down_sync(0xFFFFFFFFu, v, off);
        if (lane == 0) s_tot[wrp] = v;
        __syncthreads();
        if (tid == 0) {
            double sx = s_tot[0], sy = s_tot[1], sw = s_tot[2], sh = s_tot[3];
            double scf = s_tot[4], sno = s_tot[5], scl = s_tot[6], np = s_tot[7];
            out[0] = (float)(2.5 * sx / NCELL);
            out[1] = (float)(2.5 * sy / NCELL);
            out[2] = (float)(2.5 * sw / NCELL);
            out[3] = (float)(2.5 * sh / NCELL);
            out[4] = (float)((scf + 0.5 * sno) / NCELL);
            out[5] = (float)(scl / fmax(np * 20.0, 1.0));
            g_ctr = 0;                   // reset for next replay
        }
    }
}

extern "C" void kernel_launch(void* const* d_in, const int* in_sizes, int n_in,
                              void* d_out, int out_size) {
    const float* in = (const float*)d_in[0];   // (32,75,104,104)
    const float* tg = (const float*)d_in[1];   // (32,50,5)
    float* out = (float*)d_out;                // 6 floats

    dim3 grid(NBX, BSZ);                       // (11, 32) = 352 blocks
    yolo_fused<<<grid, 256>>>(in, tg, out);
}

// round 3
// speedup vs baseline: 3.0982x; 1.0015x over previous
#include <cuda_runtime.h>

// YOLOLoss fused single-kernel, round 3.
// Dense work = conf channels only (4.15 MB, softplus math, loads issued first);
// positive cells = per-block compacted tasks with shared-atomic accumulation.

#define BSZ     32
#define NT      50
#define HH      104
#define WW      104
#define HW      (HH*WW)                 // 10816
#define NCLS    20
#define BLK_POS 1024                    // 256 thr x 4 positions
#define NBX     ((HW + BLK_POS - 1) / BLK_POS)   // 11
#define NBLK    (NBX * BSZ)             // 352
#define NCELL   ((double)(BSZ * 3 * HW))

__device__ double   g_part[NBLK][8];
__device__ unsigned g_ctr;              // zero-init; reset by last block

// min(softplus(z), 100) == -clip(log(1 - sigmoid(z)), -100)
__device__ __forceinline__ float spl(float z) {
    return fminf(__logf(1.0f + __expf(z)), 100.0f);
}

__global__ __launch_bounds__(256) void yolo_fused(const float* __restrict__ in,
                                                  const float* __restrict__ tg,
                                                  float* __restrict__ out)
{
    __shared__ int    s_meta[NT];       // pos(14)|bn(2)|nz(3)|cls(5)
    __shared__ float  s_tx[NT], s_ty[NT], s_tw[NT], s_th[NT];
    __shared__ int    s_task[NT];       // t(6) | cm<<6
    __shared__ int    s_ign[NT];        // pos(14) | nz(3)<<14
    __shared__ int    s_ntask, s_nign, s_last;
    __shared__ float  s_acc[8];         // sx, sy, sw, sh, scf, sno, scl, np
    __shared__ double s_tot[8];

    const int b    = blockIdx.y;
    const int tid  = threadIdx.x;
    const int P0   = blockIdx.x * BLK_POS;
    const int lane = tid & 31, wrp = tid >> 5;

    // ---- 1. issue dense conf loads immediately (latency overlaps prologue) ----
    const int p0 = P0 + tid * 4;
    const bool live = (p0 < HW);        // HW%4==0 -> full quads
    const float* base = in + (size_t)b * 75 * HW;
    float4 c0, c1, c2;
    if (live) {
        c0 = *(const float4*)(base + (size_t)(0 * 25 + 4) * HW + p0);
        c1 = *(const float4*)(base + (size_t)(1 * 25 + 4) * HW + p0);
        c2 = *(const float4*)(base + (size_t)(2 * 25 + 4) * HW + p0);
    }

    if (tid < 8)  s_acc[tid] = 0.0f;
    if (tid == 0) { s_ntask = 0; s_nign = 0; }

    // ---- 2. per-target preprocessing (threads 0..49) ----
    if (tid < NT) {
        const float* t = tg + ((size_t)b * NT + tid) * 5;
        float t0 = t[0], t1 = t[1], t2 = t[2], t3 = t[3], t4 = t[4];
        int   meta = 0x7FFFFFFF;        // invalid (low14 = 16383 > any pos)
        float txv = 0.f, tyv = 0.f, twv = 0.f, thv = 0.f;
        if (t0 + t1 + t2 + t3 + t4 > 0.0f) {
            float gx = t0 * (float)WW, gy = t1 * (float)HH;
            float gw = t2 * (float)WW, gh = t3 * (float)HH;
            int gi = (int)gx, gj = (int)gy;
            const float aw[3] = {14.5f, 19.5f, 46.625f};   // ANCHORS / 8
            const float ah[3] = {11.25f, 24.75f, 40.75f};
            float area = (gw + 1.0f) * (gh + 1.0f);
            float best = -1.0f; int bn = 0, nz = 0;
            #pragma unroll
            for (int a = 0; a < 3; a++) {
                float inter = fmaxf(fminf(gw, aw[a]) + 1.0f, 0.0f) *
                              fmaxf(fminf(gh, ah[a]) + 1.0f, 0.0f);
                float iou = inter / (area + (aw[a] + 1.0f) * (ah[a] + 1.0f) - inter + 1e-16f);
                if (iou > best) { best = iou; bn = a; }
                if (iou > 0.5f) nz |= (1 << a);
            }
            txv = gx - (float)gi;
            tyv = gy - (float)gj;
            twv = __logf(gw / aw[bn] + 1e-16f);
            thv = __logf(gh / ah[bn] + 1e-16f);
            meta = (gj * WW + gi) | (bn << 14) | (nz << 16) | (((int)t4) << 19);
        }
        s_meta[tid] = meta;
        s_tx[tid] = txv; s_ty[tid] = tyv; s_tw[tid] = twv; s_th[tid] = thv;
    }
    __syncthreads();

    // ---- 3. block-filter + dedup (threads 0..49) ----
    if (tid < NT) {
        int m = s_meta[tid];
        int pos = m & 0x3FFF;
        if (pos >= P0 && pos < P0 + BLK_POS) {
            int nz = (m >> 16) & 7;
            if (nz) s_ign[atomicAdd(&s_nign, 1)] = pos | (nz << 14);

            // survivor = LAST duplicate at (pos, anchor); union class bits from earlier dups
            int mya = (m >> 14) & 3;
            unsigned cm = 1u << ((m >> 19) & 31);
            bool alive = true;
            for (int u = 0; u < NT; u++) {
                if (u == tid) continue;
                int mu = s_meta[u];
                if ((mu & 0x3FFF) == pos && ((mu >> 14) & 3) == mya) {
                    if (u > tid) alive = false;
                    else         cm |= 1u << ((mu >> 19) & 31);
                }
            }
            if (alive) s_task[atomicAdd(&s_ntask, 1)] = tid | (int)(cm << 6);
        }
    }
    __syncthreads();

    // ---- 4. dense noobj: softplus over conf, minus ignored cells ----
    float a_no = 0.0f;
    if (live) {
        int nzp = 0;                    // bit q*3+a
        const int ni = s_nign;
        for (int k = 0; k < ni; k++) {
            int e = s_ign[k];
            int d = (e & 0x3FFF) - p0;
            if ((unsigned)d < 4u) nzp |= ((e >> 14) & 7) << (d * 3);
        }
        float cv[12] = {c0.x, c0.y, c0.z, c0.w,
                        c1.x, c1.y, c1.z, c1.w,
                        c2.x, c2.y, c2.z, c2.w};
        #pragma unroll
        for (int a = 0; a < 3; a++)
            #pragma unroll
            for (int q = 0; q < 4; q++)
                if (!((nzp >> (q * 3 + a)) & 1))
                    a_no += spl(cv[a * 4 + q]);
    }
    #pragma unroll
    for (int off = 16; off > 0; off >>= 1)
        a_no += __shfl_down_sync(0xFFFFFFFFu, a_no, off);
    if (lane == 0) atomicAdd(&s_acc[5], a_no);

    // ---- 5. positive-cell tasks (<= a few threads per block) ----
    if (tid < s_ntask) {
        int e = s_task[tid];
        int t = e & 63;
        unsigned cm = ((unsigned)e) >> 6;
        int m = s_meta[t];
        int pos = m & 0x3FFF, a = (m >> 14) & 3;
        const float* ch = in + (size_t)b * 75 * HW + (size_t)(a * 25) * HW + pos;
        float vx = ch[0], vy = ch[HW], vw = ch[2 * HW], vh = ch[3 * HW], vc = ch[4 * HW];
        float pcls[NCLS];
        #pragma unroll
        for (int c = 0; c < NCLS; c++) pcls[c] = ch[(size_t)(5 + c) * HW];

        float txv = s_tx[t], tyv = s_ty[t];
        // BCE(sigm(z), t) = t*spl(-z) + (1-t)*spl(z)
        atomicAdd(&s_acc[0], txv * spl(-vx) + (1.0f - txv) * spl(vx));
        atomicAdd(&s_acc[1], tyv * spl(-vy) + (1.0f - tyv) * spl(vy));
        float dw = vw - s_tw[t], dh = vh - s_th[t];
        atomicAdd(&s_acc[2], dw * dw);
        atomicAdd(&s_acc[3], dh * dh);
        atomicAdd(&s_acc[4], spl(-vc));
        atomicAdd(&s_acc[7], 1.0f);
        float scl = 0.0f;
        #pragma unroll
        for (int c = 0; c < NCLS; c++) {
            float z = ((cm >> c) & 1) ? -pcls[c] : pcls[c];
            scl += spl(z);
        }
        atomicAdd(&s_acc[6], scl);
    }
    __syncthreads();

    // ---- 6. write block partial, last block finalizes ----
    const int gb = b * NBX + blockIdx.x;
    if (tid < 8) g_part[gb][tid] = (double)s_acc[tid];
    __threadfence();
    __syncthreads();
    if (tid == 0) s_last = (atomicAdd(&g_ctr, 1) == NBLK - 1);
    __syncthreads();

    if (s_last) {
        __threadfence();
        double v = 0.0;                  // warp wrp owns accumulator wrp
        for (int i = lane; i < NBLK; i += 32) v += g_part[i][wrp];
        #pragma unroll
        for (int off = 16; off > 0; off >>= 1)
            v += __shfl_down_sync(0xFFFFFFFFu, v, off);
        if (lane == 0) s_tot[wrp] = v;
        __syncthreads();
        if (tid == 0) {
            double sx = s_tot[0], sy = s_tot[1], sw = s_tot[2], sh = s_tot[3];
            double scf = s_tot[4], sno = s_tot[5], scl = s_tot[6], np = s_tot[7];
            out[0] = (float)(2.5 * sx / NCELL);
            out[1] = (float)(2.5 * sy / NCELL);
            out[2] = (float)(2.5 * sw / NCELL);
            out[3] = (float)(2.5 * sh / NCELL);
            out[4] = (float)((scf + 0.5 * sno) / NCELL);
            out[5] = (float)(scl / fmax(np * 20.0, 1.0));
            g_ctr = 0;                   // reset for next graph replay
        }
    }
}

extern "C" void kernel_launch(void* const* d_in, const int* in_sizes, int n_in,
                              void* d_out, int out_size) {
    const float* in = (const float*)d_in[0];   // (32,75,104,104)
    const float* tg = (const float*)d_in[1];   // (32,50,5)
    float* out = (float*)d_out;                // 6 floats

    dim3 grid(NBX, BSZ);                       // (11, 32) = 352 blocks
    yolo_fused<<<grid, 256>>>(in, tg, out);
}

// round 4
// speedup vs baseline: 3.8265x; 1.2351x over previous
#include <cuda_runtime.h>

// YOLOLoss fused, round 4: dense path fully decoupled from target processing.
// Dense = sum softplus(conf) over ALL cells (no mask dependency); ignored cells
// are subtracted by their owning target thread. Positives handled by the thread
// that owns the target (speculative loads issued pre-barrier).

#define BSZ     32
#define NT      50
#define HH      104
#define WW      104
#define HW      (HH*WW)                 // 10816
#define NCLS    20
#define BLK_POS 512                     // 256 thr x 2 positions
#define NBX     ((HW + BLK_POS - 1) / BLK_POS)   // 22
#define NBLK    (NBX * BSZ)             // 704
#define NCELL   ((double)(BSZ * 3 * HW))

__device__ double   g_acc[8];           // sx, sy, sw, sh, scf, sno, scl, np (zero-init)
__device__ unsigned g_ctr;              // zero-init; reset by last block

// min(softplus(z), 100) == -clip(log(1 - sigmoid(z)), -100);  spl(-z) for log(p)
__device__ __forceinline__ float spl(float z) {
    return fminf(__logf(1.0f + __expf(z)), 100.0f);
}

__global__ __launch_bounds__(256)
void yolo_fused(const float* __restrict__ in, const float* __restrict__ tg,
                float* __restrict__ out)
{
    __shared__ int   s_meta[NT];        // pos(14)|bn(2)|nz(3)|cls(5)
    __shared__ float s_acc[8];
    __shared__ int   s_last;

    const int b    = blockIdx.y;
    const int tid  = threadIdx.x;
    const int P0   = blockIdx.x * BLK_POS;
    const int lane = tid & 31;

    // ---- dense conf loads: 2 positions x 3 anchors, issued first ----
    const int  p0   = P0 + tid * 2;
    const bool live = (p0 < HW);        // HW even -> full pairs
    const float* base = in + (size_t)b * 75 * HW;
    float2 c0, c1, c2;
    if (live) {
        c0 = *(const float2*)(base + (size_t)( 4) * HW + p0);
        c1 = *(const float2*)(base + (size_t)(29) * HW + p0);
        c2 = *(const float2*)(base + (size_t)(54) * HW + p0);
    }
    if (tid < 8) s_acc[tid] = 0.0f;

    // ---- per-target prologue (threads 0..49), own meta kept in registers ----
    int  mymeta = 0;
    bool inr = false;
    float mytx = 0.f, myty = 0.f, mytw = 0.f, myth = 0.f;
    if (tid < NT) {
        const float* t = tg + ((size_t)b * NT + tid) * 5;
        float t0 = t[0], t1 = t[1], t2 = t[2], t3 = t[3], t4 = t[4];
        int meta = 0x7FFFFFFF;          // invalid: low14 = 16383 > any pos
        if (t0 + t1 + t2 + t3 + t4 > 0.0f) {
            float gx = t0 * (float)WW, gy = t1 * (float)HH;
            float gw = t2 * (float)WW, gh = t3 * (float)HH;
            int gi = (int)gx, gj = (int)gy;
            const float aw[3] = {14.5f, 19.5f, 46.625f};   // ANCHORS / 8
            const float ah[3] = {11.25f, 24.75f, 40.75f};
            float area = (gw + 1.0f) * (gh + 1.0f);
            float best = -1.0f; int bn = 0, nz = 0;
            #pragma unroll
            for (int a = 0; a < 3; a++) {
                float inter = fmaxf(fminf(gw, aw[a]) + 1.0f, 0.0f) *
                              fmaxf(fminf(gh, ah[a]) + 1.0f, 0.0f);
                float iou = inter / (area + (aw[a] + 1.0f) * (ah[a] + 1.0f) - inter + 1e-16f);
                if (iou > best) { best = iou; bn = a; }      // first max wins
                if (iou > 0.5f) nz |= (1 << a);
            }
            mytx = gx - (float)gi;
            myty = gy - (float)gj;
            mytw = __logf(gw / aw[bn] + 1e-16f);
            myth = __logf(gh / ah[bn] + 1e-16f);
            int pos = gj * WW + gi;
            meta = pos | (bn << 14) | (nz << 16) | (((int)t4) << 19);
            inr = (pos >= P0) && (pos < P0 + BLK_POS);
        }
        s_meta[tid] = meta;
        mymeta = meta;
    }

    // ---- speculative loads for in-range targets (pre-barrier, overlaps scan) ----
    float vx = 0, vy = 0, vw = 0, vh = 0, vc = 0, cfa0 = 0, cfa1 = 0, cfa2 = 0;
    int   mypos = 0, mya = 0;
    if (inr) {
        mypos = mymeta & 0x3FFF;
        mya   = (mymeta >> 14) & 3;
        const float* ch = base + (size_t)(mya * 25) * HW + mypos;
        vx = ch[0]; vy = ch[HW]; vw = ch[2 * HW]; vh = ch[3 * HW]; vc = ch[4 * HW];
        cfa0 = base[(size_t)( 4) * HW + mypos];
        cfa1 = base[(size_t)(29) * HW + mypos];
        cfa2 = base[(size_t)(54) * HW + mypos];
    }

    // ---- dense math: independent of targets (no mask!), before barrier ----
    float a_no = 0.0f;
    if (live)
        a_no = spl(c0.x) + spl(c0.y) + spl(c1.x) + spl(c1.y) + spl(c2.x) + spl(c2.y);
    #pragma unroll
    for (int off = 16; off > 0; off >>= 1)
        a_no += __shfl_down_sync(0xFFFFFFFFu, a_no, off);

    __syncthreads();                    // orders s_acc zero + s_meta
    if (lane == 0 && a_no != 0.0f) atomicAdd(&s_acc[5], a_no);

    // ---- target resolution: dedup survivors, class union, unique ignore bits ----
    if (inr) {
        int      mynz  = (mymeta >> 16) & 7;
        unsigned cm    = 1u << ((mymeta >> 19) & 31);
        bool     alive = true;
        int      subnz = mynz;          // ignore bits this thread uniquely owns
        for (int u = 0; u < NT; u++) {
            if (u == tid) continue;
            int mu = s_meta[u];
            if ((mu & 0x3FFF) != mypos) continue;
            if (((mu >> 14) & 3) == mya) {
                if (u > tid) alive = false;                  // last duplicate wins
                else         cm |= 1u << ((mu >> 19) & 31);  // union earlier classes
            }
            if (u < tid) subnz &= ~((mu >> 16) & 7);         // earlier owner subtracts
        }
        float sub = 0.0f;               // remove ignored cells from dense sum
        if (subnz & 1) sub += spl(cfa0);
        if (subnz & 2) sub += spl(cfa1);
        if (subnz & 4) sub += spl(cfa2);
        if (sub != 0.0f) atomicAdd(&s_acc[5], -sub);

        if (alive) {
            const float* ch = base + (size_t)(mya * 25) * HW + mypos;
            float pc[NCLS];
            #pragma unroll
            for (int c = 0; c < NCLS; c++) pc[c] = ch[(size_t)(5 + c) * HW];
            float scl = 0.0f;
            #pragma unroll
            for (int c = 0; c < NCLS; c++)
                scl += spl(((cm >> c) & 1) ? -pc[c] : pc[c]);
            // BCE(sigm(z), t) = t*spl(-z) + (1-t)*spl(z)
            atomicAdd(&s_acc[0], mytx * spl(-vx) + (1.0f - mytx) * spl(vx));
            atomicAdd(&s_acc[1], myty * spl(-vy) + (1.0f - myty) * spl(vy));
            float dw = vw - mytw, dh = vh - myth;
            atomicAdd(&s_acc[2], dw * dw);
            atomicAdd(&s_acc[3], dh * dh);
            atomicAdd(&s_acc[4], spl(-vc));
            atomicAdd(&s_acc[6], scl);
            atomicAdd(&s_acc[7], 1.0f);
        }
    }
    __syncthreads();

    // ---- global accumulation + last-block finalize ----
    if (tid < 8) {
        float v = s_acc[tid];
        if (v != 0.0f) atomicAdd(&g_acc[tid], (double)v);
    }
    __threadfence();
    __syncthreads();
    if (tid == 0) s_last = (atomicAdd(&g_ctr, 1) == NBLK - 1);
    __syncthreads();

    if (s_last && tid == 0) {
        __threadfence();
        double A[8];
        #pragma unroll
        for (int i = 0; i < 8; i++) A[i] = atomicAdd(&g_acc[i], 0.0);  // coherent read
        out[0] = (float)(2.5 * A[0] / NCELL);
        out[1] = (float)(2.5 * A[1] / NCELL);
        out[2] = (float)(2.5 * A[2] / NCELL);
        out[3] = (float)(2.5 * A[3] / NCELL);
        out[4] = (float)((A[4] + 0.5 * A[5]) / NCELL);
        out[5] = (float)(A[6] / fmax(A[7] * 20.0, 1.0));
        #pragma unroll
        for (int i = 0; i < 8; i++) g_acc[i] = 0.0;    // reset for next replay
        __threadfence();
        g_ctr = 0;
    }
}

extern "C" void kernel_launch(void* const* d_in, const int* in_sizes, int n_in,
                              void* d_out, int out_size) {
    const float* in = (const float*)d_in[0];   // (32,75,104,104)
    const float* tg = (const float*)d_in[1];   // (32,50,5)
    float* out = (float*)d_out;                // 6 floats

    dim3 grid(NBX, BSZ);                       // (22, 32) = 704 blocks
    yolo_fused<<<grid, 256>>>(in, tg, out);
}